// round 5
// baseline (speedup 1.0000x reference)
#include <cuda_runtime.h>
#include <cstdint>

#define BB   512      // batch
#define LL   512      // leaves
#define EE   128      // emb
#define OPS  5
#define NI   511      // internal nodes
#define RPC  4        // batch rows per CTA

// scratch: all node embeddings [B][NI][E]  (~134 MB)
__device__ float g_nodes[(size_t)BB * NI * EE];

// ---------------- packed f32x2 helpers ----------------
__device__ __forceinline__ unsigned long long pack2(float lo, float hi) {
    unsigned long long r;
    asm("mov.b64 %0, {%1, %2};" : "=l"(r) : "f"(lo), "f"(hi));
    return r;
}
__device__ __forceinline__ void fma2(unsigned long long& d, unsigned long long a, unsigned long long b) {
    asm("fma.rn.f32x2 %0, %1, %2, %0;" : "+l"(d) : "l"(a), "l"(b));
}
__device__ __forceinline__ unsigned long long add2(unsigned long long a, unsigned long long b) {
    unsigned long long r;
    asm("add.rn.f32x2 %0, %1, %2;" : "=l"(r) : "l"(a), "l"(b));
    return r;
}
__device__ __forceinline__ float2 unpack2(unsigned long long v) {
    float2 f;
    asm("mov.b64 {%0, %1}, %2;" : "=f"(f.x), "=f"(f.y) : "l"(v));
    return f;
}
__device__ __forceinline__ uint32_t smem_u32(const void* p) {
    uint32_t a;
    asm("{ .reg .u64 t; cvta.to.shared.u64 t, %1; cvt.u32.u64 %0, t; }" : "=r"(a) : "l"(p));
    return a;
}
// LDS.128 -> two b64 register pairs (two f32x2 operands = 4 floats)
__device__ __forceinline__ void lds128_pair(unsigned long long& a, unsigned long long& b, uint32_t addr) {
    asm volatile("ld.shared.v2.u64 {%0, %1}, [%2];" : "=l"(a), "=l"(b) : "r"(addr));
}

// ---------------- sequential recurrence ----------------
// 512 threads: h = t&3 (K quarter, interleaved 16B chunks), n = t>>2 (0..127).
// Thread computes ONE output column n over a 64-float K slice (32 left + 32
// right). Weight slice = 32 b64 regs. 4 warps/SMSP for latency hiding.
// Chunk i of slice h covers floats k = 4h+16i..+3 (i = 0..7) on each side.
// Reduction over the 4 h-lanes: two scalar shfl_xor, no selects, no packing.
__global__ void __launch_bounds__(512, 1) recur_kernel(
    const float* __restrict__ emb,   // [B, L, E]
    const float* __restrict__ Ww,    // [2E, E]
    const float* __restrict__ Wb,    // [E]
    const int*   __restrict__ li,    // [NI]
    const int*   __restrict__ ri)    // [NI]
{
    __shared__ __align__(16) float cur[2][RPC][EE];    // double-buffered state
    __shared__ __align__(16) float leafs[2][RPC][EE];  // double-buffered right leaf
    __shared__ int ridx[NI + 1];

    const int t  = threadIdx.x;
    const int h  = t & 3;           // K-slice
    const int n  = t >> 2;          // output column 0..127
    const int b0 = blockIdx.x * RPC;

    // Weight slice in registers: 2 sides x 32 K-floats = 32 b64 (64 regs).
    unsigned long long wl[16], wr[16];
#pragma unroll
    for (int i = 0; i < 8; i++) {
        const int k0 = 4 * h + 16 * i;
        wl[2*i]   = pack2(Ww[(size_t)(k0    ) * EE + n], Ww[(size_t)(k0 + 1) * EE + n]);
        wl[2*i+1] = pack2(Ww[(size_t)(k0 + 2) * EE + n], Ww[(size_t)(k0 + 3) * EE + n]);
        wr[2*i]   = pack2(Ww[(size_t)(EE + k0    ) * EE + n], Ww[(size_t)(EE + k0 + 1) * EE + n]);
        wr[2*i+1] = pack2(Ww[(size_t)(EE + k0 + 2) * EE + n], Ww[(size_t)(EE + k0 + 3) * EE + n]);
    }
    const float biasv = Wb[n];

    // right-leaf indices into smem
    for (int j = t; j < NI; j += 512) ridx[j] = ri[j];
    if (t == 0) ridx[NI] = ri[0];   // dummy for prefetch overrun

    // init cur[0] = leaf(left_idx[0]); loader: 4 rows x 128 cols, 1 float each
    const int l0   = li[0];
    const int r_ld = t >> 7;
    const int c_ld = t & 127;
    cur[0][r_ld][c_ld] = emb[((size_t)(b0 + r_ld) * LL + l0) * EE + c_ld];
    __syncthreads();

    // prefetch right leaf for step 0
    float lv = emb[((size_t)(b0 + r_ld) * LL + ridx[0]) * EE + c_ld];

    const uint32_t cur_base  = smem_u32(cur);
    const uint32_t leaf_base = smem_u32(leafs);
    const uint32_t hoff = (uint32_t)(h * 16);

    for (int j = 0; j < NI; j++) {
        const int rb = j & 1;           // read state buffer
        const int wb = rb ^ 1;          // write state buffer
        // commit prefetched leaf; one barrier covers leaf-ready + prev cur writes
        leafs[rb][r_ld][c_ld] = lv;
        const int rnext = ridx[j + 1];
        __syncthreads();
        lv = emb[((size_t)(b0 + r_ld) * LL + rnext) * EE + c_ld];

#pragma unroll
        for (int r = 0; r < RPC; r++) {
            unsigned long long s0 = 0ull, s1 = 0ull;
            const uint32_t xl = cur_base  + (uint32_t)(((rb * RPC + r) * EE) * 4) + hoff;
            const uint32_t xr = leaf_base + (uint32_t)(((rb * RPC + r) * EE) * 4) + hoff;
#pragma unroll
            for (int i = 0; i < 8; i++) {
                unsigned long long p0, p1;
                lds128_pair(p0, p1, xl + i * 64);
                fma2(s0, p0, wl[2*i]);
                fma2(s1, p1, wl[2*i+1]);
            }
#pragma unroll
            for (int i = 0; i < 8; i++) {
                unsigned long long p0, p1;
                lds128_pair(p0, p1, xr + i * 64);
                fma2(s0, p0, wr[2*i]);
                fma2(s1, p1, wr[2*i+1]);
            }
            // horizontal within thread, then across the 4 h-lanes of the quad
            const float2 f = unpack2(add2(s0, s1));
            float u = f.x + f.y;
            u += __shfl_xor_sync(0xFFFFFFFFu, u, 1);
            u += __shfl_xor_sync(0xFFFFFFFFu, u, 2);   // all 4 h-lanes hold y[r][n]
            if (h == r) {
                const float v = u + biasv;
                cur[wb][r][n] = v;
                g_nodes[((size_t)(b0 + r) * NI + j) * EE + n] = v;
            }
        }
    }
}

// ---------------- parallel projection: op = node @ G_w + G_b ----------------
// 2 nodes per warp (2 outstanding LDG.128 -> DRAM latency shared)
__global__ void __launch_bounds__(256) proj_kernel(
    const float* __restrict__ Gw,   // [E, OPS]
    const float* __restrict__ Gb,   // [OPS]
    float* __restrict__ out,        // [B, NI, OPS]
    int total_pairs)
{
    __shared__ float gws[EE * OPS];
    __shared__ float gbs[OPS];
    const int t = threadIdx.x;
    for (int i = t; i < EE * OPS; i += blockDim.x) gws[i] = Gw[i];
    if (t < OPS) gbs[t] = Gb[t];
    __syncthreads();

    const int pair = blockIdx.x * (blockDim.x >> 5) + (t >> 5);
    if (pair >= total_pairs) return;
    const int lane  = t & 31;
    const size_t n0 = (size_t)pair * 2;

    const float4 x0 = *(const float4*)&g_nodes[n0 * EE + lane * 4];
    const float4 x1 = *(const float4*)&g_nodes[(n0 + 1) * EE + lane * 4];
    const float* g  = &gws[lane * 4 * OPS];

    float p0[OPS], p1[OPS];
#pragma unroll
    for (int o = 0; o < OPS; o++) {
        p0[o] = x0.x * g[o] + x0.y * g[OPS + o] + x0.z * g[2 * OPS + o] + x0.w * g[3 * OPS + o];
        p1[o] = x1.x * g[o] + x1.y * g[OPS + o] + x1.z * g[2 * OPS + o] + x1.w * g[3 * OPS + o];
    }
#pragma unroll
    for (int off = 16; off; off >>= 1)
#pragma unroll
        for (int o = 0; o < OPS; o++) {
            p0[o] += __shfl_xor_sync(0xFFFFFFFFu, p0[o], off);
            p1[o] += __shfl_xor_sync(0xFFFFFFFFu, p1[o], off);
        }

    if (lane == 0) {
        float* op = out + n0 * OPS;
#pragma unroll
        for (int o = 0; o < OPS; o++) { op[o] = p0[o] + gbs[o]; op[OPS + o] = p1[o] + gbs[o]; }
    }
}

// ---------------- labels tail ----------------
// Labels land on device as int32 (JAX x64 disabled). mode 1: float cast.
// mode 2: widen to raw int64.
__global__ void tail_kernel(const int* __restrict__ labels, float* __restrict__ out, int mode)
{
    const int j = blockIdx.x * blockDim.x + threadIdx.x;
    if (j >= NI) return;
    const size_t base = (size_t)BB * NI * OPS;
    if (mode == 1) {
        out[base + j] = (float)labels[j];
    } else {
        ((long long*)(out + base))[j] = (long long)labels[j];
    }
}

extern "C" void kernel_launch(void* const* d_in, const int* in_sizes, int n_in,
                              void* d_out, int out_size)
{
    const float* emb    = (const float*)d_in[0];
    const float* Ww     = (const float*)d_in[1];
    const float* Wb     = (const float*)d_in[2];
    const float* Gw     = (const float*)d_in[3];
    const float* Gb     = (const float*)d_in[4];
    const int*   li     = (const int*)d_in[5];
    const int*   ri     = (const int*)d_in[6];
    const int*   labels = (const int*)d_in[7];
    float*       out    = (float*)d_out;

    recur_kernel<<<BB / RPC, 512>>>(emb, Ww, Wb, li, ri);

    const int total_pairs = BB * NI / 2;                    // 130816
    proj_kernel<<<total_pairs / 8, 256>>>(Gw, Gb, out, total_pairs); // 8 warps/block

    const long long base = (long long)BB * NI * OPS;
    const long long tail = (long long)out_size - base;
    if (tail == NI)          tail_kernel<<<2, 256>>>(labels, out, 1);
    else if (tail == 2 * NI) tail_kernel<<<2, 256>>>(labels, out, 2);
}

// round 6
// speedup vs baseline: 1.0123x; 1.0123x over previous
#include <cuda_runtime.h>
#include <cstdint>

#define BB   512      // batch
#define LL   512      // leaves
#define EE   128      // emb
#define OPS  5
#define NI   511      // internal nodes
#define RPC  4        // batch rows per CTA

// scratch: all node embeddings [B][NI][E] (~134 MB)
__device__ float g_nodes[(size_t)BB * NI * EE];
// scratch: right-side contributions per leaf: rhs[b][l] = emb[b,l] @ W_r + Wb (~134 MB)
__device__ float g_rhs[(size_t)BB * LL * EE];

// ---------------- packed f32x2 helpers ----------------
__device__ __forceinline__ unsigned long long pack2(float lo, float hi) {
    unsigned long long r;
    asm("mov.b64 %0, {%1, %2};" : "=l"(r) : "f"(lo), "f"(hi));
    return r;
}
__device__ __forceinline__ void fma2(unsigned long long& d, unsigned long long a, unsigned long long b) {
    asm("fma.rn.f32x2 %0, %1, %2, %0;" : "+l"(d) : "l"(a), "l"(b));
}
__device__ __forceinline__ unsigned long long add2(unsigned long long a, unsigned long long b) {
    unsigned long long r;
    asm("add.rn.f32x2 %0, %1, %2;" : "=l"(r) : "l"(a), "l"(b));
    return r;
}
__device__ __forceinline__ float2 unpack2(unsigned long long v) {
    float2 f;
    asm("mov.b64 {%0, %1}, %2;" : "=f"(f.x), "=f"(f.y) : "l"(v));
    return f;
}
__device__ __forceinline__ uint32_t smem_u32(const void* p) {
    uint32_t a;
    asm("{ .reg .u64 t; cvta.to.shared.u64 t, %1; cvt.u32.u64 %0, t; }" : "=r"(a) : "l"(p));
    return a;
}
// LDS.128 -> two b64 register pairs (two f32x2 operands = 4 floats)
__device__ __forceinline__ void lds128_pair(unsigned long long& a, unsigned long long& b, uint32_t addr) {
    asm volatile("ld.shared.v2.u64 {%0, %1}, [%2];" : "=l"(a), "=l"(b) : "r"(addr));
}
__device__ __forceinline__ unsigned long long shfl_xor64(unsigned long long v, int m) {
    return __shfl_xor_sync(0xFFFFFFFFu, v, m);
}

// =================== rhs GEMM: g_rhs[m] = emb[m] @ W_r + Wb ===================
// M = B*LL = 262144, N = 128, K = 128. Tile: 128 rows/CTA, full N.
// 256 threads: tx = t&7 (cols tx*16..+15), ty = t>>3 (rows ty*4..+3).
// Thread tile 4x16, acc in f32x2 pairs (64 regs). K chunked by 32, W chunk +
// x chunk staged in smem (34 KB static -> 2 CTAs/SM).
__global__ void __launch_bounds__(256, 2) rhs_kernel(
    const float* __restrict__ emb,   // [B*LL, E]
    const float* __restrict__ Ww,    // [2E, E]; rows 128..255 = W_r
    const float* __restrict__ Wb)    // [E]
{
    __shared__ __align__(16) float Wsc[32 * 128];   // W_r chunk [32 k][128 n]
    __shared__ __align__(16) float xs[128 * 36];    // x chunk [128 m][32 k + pad]

    const int t  = threadIdx.x;
    const int tx = t & 7;
    const int ty = t >> 3;
    const int m0 = blockIdx.x * 128;
    const int n0 = tx * 16;

    unsigned long long wb2[8];
#pragma unroll
    for (int c = 0; c < 8; c++)
        wb2[c] = pack2(Wb[n0 + 2 * c], Wb[n0 + 2 * c + 1]);

    unsigned long long acc[4][8];
#pragma unroll
    for (int j = 0; j < 4; j++)
#pragma unroll
        for (int c = 0; c < 8; c++) acc[j][c] = 0ull;

    const float4* emb4 = (const float4*)emb;
    const float4* Ww4  = (const float4*)Ww;
    const uint32_t ws_base = smem_u32(Wsc);
    const uint32_t xs_base = smem_u32(xs);

    for (int kc = 0; kc < 4; kc++) {
        __syncthreads();
        // stage W_r chunk: rows (128 + kc*32 + kw), all 128 cols
#pragma unroll
        for (int ii = 0; ii < 4; ii++) {
            const int idx = t + 256 * ii;
            const int kw  = idx >> 5;
            const int n4  = idx & 31;
            ((float4*)Wsc)[kw * 32 + n4] = Ww4[4096 + (size_t)(kc * 32 + kw) * 32 + n4];
        }
        // stage x chunk: 128 rows x 32 k
#pragma unroll
        for (int ii = 0; ii < 4; ii++) {
            const int idx = t + 256 * ii;
            const int m   = idx >> 3;
            const int f4  = idx & 7;
            const float4 v = emb4[(size_t)(m0 + m) * 32 + kc * 8 + f4];
            *(float4*)&xs[m * 36 + f4 * 4] = v;
        }
        __syncthreads();

#pragma unroll
        for (int kk = 0; kk < 32; kk++) {
            unsigned long long b[8];
            const uint32_t wrow = ws_base + (uint32_t)((kk * 128 + n0) * 4);
            lds128_pair(b[0], b[1], wrow);
            lds128_pair(b[2], b[3], wrow + 16);
            lds128_pair(b[4], b[5], wrow + 32);
            lds128_pair(b[6], b[7], wrow + 48);
            float a[4];
#pragma unroll
            for (int j = 0; j < 4; j++) {
                asm volatile("ld.shared.f32 %0, [%1];" : "=f"(a[j])
                             : "r"(xs_base + (uint32_t)(((ty * 4 + j) * 36 + kk) * 4)));
            }
#pragma unroll
            for (int j = 0; j < 4; j++) {
                const unsigned long long a2 = pack2(a[j], a[j]);
#pragma unroll
                for (int c = 0; c < 8; c++) fma2(acc[j][c], b[c], a2);
            }
        }
    }

    // epilogue: add bias, store
#pragma unroll
    for (int j = 0; j < 4; j++) {
        float* orow = &g_rhs[(size_t)(m0 + ty * 4 + j) * EE + n0];
#pragma unroll
        for (int c = 0; c < 8; c++) {
            const float2 f = unpack2(add2(acc[j][c], wb2[c]));
            orow[2 * c]     = f.x;
            orow[2 * c + 1] = f.y;
        }
    }
}

// =================== sequential recurrence: y = cur @ W_l + rhs ===================
// 256 threads: h = t&3 (K quarter, interleaved 16B chunks), n = t>>2 (0..63).
// Thread computes output cols nA=n, nB=n+64 over its 32-float K slice of W_l.
// rhs (incl. bias) prefetched from gmem one step ahead. 2 warps/SMSP.
__global__ void __launch_bounds__(256, 1) recur_kernel(
    const float* __restrict__ emb,   // [B, L, E]
    const float* __restrict__ Ww,    // [2E, E]; rows 0..127 = W_l
    const int*   __restrict__ li,    // [NI]
    const int*   __restrict__ ri)    // [NI]
{
    __shared__ __align__(16) float cur[2][RPC][EE];    // double-buffered state
    __shared__ int ridx[NI + 1];

    const int t  = threadIdx.x;
    const int h  = t & 3;           // K-slice
    const int n  = t >> 2;          // 0..63
    const int nA = n;
    const int nB = n + 64;
    const int b0 = blockIdx.x * RPC;

    // W_l column slices: 2 cols x 32 K-floats = 32 b64 regs.
    unsigned long long wlA[16], wlB[16];
#pragma unroll
    for (int i = 0; i < 8; i++) {
        const int k0 = 4 * h + 16 * i;
        wlA[2*i]   = pack2(Ww[(size_t)(k0    ) * EE + nA], Ww[(size_t)(k0 + 1) * EE + nA]);
        wlA[2*i+1] = pack2(Ww[(size_t)(k0 + 2) * EE + nA], Ww[(size_t)(k0 + 3) * EE + nA]);
        wlB[2*i]   = pack2(Ww[(size_t)(k0    ) * EE + nB], Ww[(size_t)(k0 + 1) * EE + nB]);
        wlB[2*i+1] = pack2(Ww[(size_t)(k0 + 2) * EE + nB], Ww[(size_t)(k0 + 3) * EE + nB]);
    }

    // right-leaf indices into smem
    for (int j = t; j < NI; j += 256) ridx[j] = ri[j];
    if (t == 0) ridx[NI] = ri[0];   // dummy for prefetch overrun

    // init cur[0] = leaf(left_idx[0]); loader: 4 rows x 64 lanes x float2
    const int l0   = li[0];
    const int r_ld = t >> 6;
    const int c_ld = (t & 63) * 2;
    {
        const float2 v = *(const float2*)&emb[((size_t)(b0 + r_ld) * LL + l0) * EE + c_ld];
        cur[0][r_ld][c_ld]     = v.x;
        cur[0][r_ld][c_ld + 1] = v.y;
    }
    __syncthreads();

    // prefetch rhs for step 0 (row b0+h: the row this thread commits)
    const float* rr = &g_rhs[((size_t)(b0 + h) * LL + ridx[0]) * EE];
    float rv0 = rr[nA];
    float rv1 = rr[nB];

    const uint32_t cur_base = smem_u32(cur);
    const uint32_t hoff = (uint32_t)(h * 16);

    for (int j = 0; j < NI; j++) {
        const int rb = j & 1;
        const int wb = rb ^ 1;
        const int lnext = ridx[j + 1];
        __syncthreads();                 // prev step's cur[wb] stores visible
        // prefetch rhs for step j+1
        const float* rn = &g_rhs[((size_t)(b0 + h) * LL + lnext) * EE];
        const float nv0 = rn[nA];
        const float nv1 = rn[nB];

#pragma unroll
        for (int r = 0; r < RPC; r++) {
            unsigned long long sA0 = 0ull, sA1 = 0ull, sB0 = 0ull, sB1 = 0ull;
            const uint32_t xl = cur_base + (uint32_t)(((rb * RPC + r) * EE) * 4) + hoff;
#pragma unroll
            for (int i = 0; i < 8; i++) {
                unsigned long long p0, p1;
                lds128_pair(p0, p1, xl + i * 64);
                fma2(sA0, p0, wlA[2*i]); fma2(sA1, p1, wlA[2*i+1]);
                fma2(sB0, p0, wlB[2*i]); fma2(sB1, p1, wlB[2*i+1]);
            }
            const float2 fA = unpack2(add2(sA0, sA1));
            const float2 fB = unpack2(add2(sB0, sB1));
            unsigned long long u = pack2(fA.x + fA.y, fB.x + fB.y);
            u = add2(u, shfl_xor64(u, 1));
            u = add2(u, shfl_xor64(u, 2));       // all 4 h-lanes hold (yA,yB) partial-left
            if (h == r) {
                u = add2(u, pack2(rv0, rv1));    // + rhs (incl bias)
                const float2 y = unpack2(u);
                cur[wb][r][nA] = y.x;
                cur[wb][r][nB] = y.y;
                float* gn = &g_nodes[((size_t)(b0 + r) * NI + j) * EE];
                gn[nA] = y.x;
                gn[nB] = y.y;
            }
        }
        rv0 = nv0;
        rv1 = nv1;
    }
}

// ---------------- parallel projection: op = node @ G_w + G_b ----------------
__global__ void __launch_bounds__(256) proj_kernel(
    const float* __restrict__ Gw,   // [E, OPS]
    const float* __restrict__ Gb,   // [OPS]
    float* __restrict__ out,        // [B, NI, OPS]
    int total_pairs)
{
    __shared__ float gws[EE * OPS];
    __shared__ float gbs[OPS];
    const int t = threadIdx.x;
    for (int i = t; i < EE * OPS; i += blockDim.x) gws[i] = Gw[i];
    if (t < OPS) gbs[t] = Gb[t];
    __syncthreads();

    const int pair = blockIdx.x * (blockDim.x >> 5) + (t >> 5);
    if (pair >= total_pairs) return;
    const int lane  = t & 31;
    const size_t n0 = (size_t)pair * 2;

    const float4 x0 = *(const float4*)&g_nodes[n0 * EE + lane * 4];
    const float4 x1 = *(const float4*)&g_nodes[(n0 + 1) * EE + lane * 4];
    const float* g  = &gws[lane * 4 * OPS];

    float p0[OPS], p1[OPS];
#pragma unroll
    for (int o = 0; o < OPS; o++) {
        p0[o] = x0.x * g[o] + x0.y * g[OPS + o] + x0.z * g[2 * OPS + o] + x0.w * g[3 * OPS + o];
        p1[o] = x1.x * g[o] + x1.y * g[OPS + o] + x1.z * g[2 * OPS + o] + x1.w * g[3 * OPS + o];
    }
#pragma unroll
    for (int off = 16; off; off >>= 1)
#pragma unroll
        for (int o = 0; o < OPS; o++) {
            p0[o] += __shfl_xor_sync(0xFFFFFFFFu, p0[o], off);
            p1[o] += __shfl_xor_sync(0xFFFFFFFFu, p1[o], off);
        }

    if (lane == 0) {
        float* op = out + n0 * OPS;
#pragma unroll
        for (int o = 0; o < OPS; o++) { op[o] = p0[o] + gbs[o]; op[OPS + o] = p1[o] + gbs[o]; }
    }
}

// ---------------- labels tail ----------------
__global__ void tail_kernel(const int* __restrict__ labels, float* __restrict__ out, int mode)
{
    const int j = blockIdx.x * blockDim.x + threadIdx.x;
    if (j >= NI) return;
    const size_t base = (size_t)BB * NI * OPS;
    if (mode == 1) {
        out[base + j] = (float)labels[j];
    } else {
        ((long long*)(out + base))[j] = (long long)labels[j];
    }
}

extern "C" void kernel_launch(void* const* d_in, const int* in_sizes, int n_in,
                              void* d_out, int out_size)
{
    const float* emb    = (const float*)d_in[0];
    const float* Ww     = (const float*)d_in[1];
    const float* Wb     = (const float*)d_in[2];
    const float* Gw     = (const float*)d_in[3];
    const float* Gb     = (const float*)d_in[4];
    const int*   li     = (const int*)d_in[5];
    const int*   ri     = (const int*)d_in[6];
    const int*   labels = (const int*)d_in[7];
    float*       out    = (float*)d_out;

    // 1) right-side GEMM (fully parallel, incl. bias)
    rhs_kernel<<<(BB * LL) / 128, 256>>>(emb, Ww, Wb);

    // 2) sequential recurrence (left half only)
    recur_kernel<<<BB / RPC, 256>>>(emb, Ww, li, ri);

    // 3) output projection
    const int total_pairs = BB * NI / 2;                    // 130816
    proj_kernel<<<total_pairs / 8, 256>>>(Gw, Gb, out, total_pairs);

    // 4) labels passthrough if the output buffer expects it
    const long long base = (long long)BB * NI * OPS;
    const long long tail = (long long)out_size - base;
    if (tail == NI)          tail_kernel<<<2, 256>>>(labels, out, 1);
    else if (tail == 2 * NI) tail_kernel<<<2, 256>>>(labels, out, 2);
}

// round 7
// speedup vs baseline: 1.7370x; 1.7159x over previous
#include <cuda_runtime.h>
#include <cstdint>

#define BB   512      // batch
#define LL   512      // leaves
#define EE   128      // emb
#define OPS  5
#define NI   511      // internal nodes
#define RPC  4        // batch rows per CTA

typedef unsigned long long ull;

// scratch: all node embeddings [B][NI][E]  (~134 MB)
__device__ float g_nodes[(size_t)BB * NI * EE];

// ---------------- packed f32x2 helpers ----------------
__device__ __forceinline__ ull pack2(float lo, float hi) {
    ull r;
    asm("mov.b64 %0, {%1, %2};" : "=l"(r) : "f"(lo), "f"(hi));
    return r;
}
__device__ __forceinline__ void fma2(ull& d, ull a, ull b) {
    asm("fma.rn.f32x2 %0, %1, %2, %0;" : "+l"(d) : "l"(a), "l"(b));
}
__device__ __forceinline__ ull add2(ull a, ull b) {
    ull r;
    asm("add.rn.f32x2 %0, %1, %2;" : "=l"(r) : "l"(a), "l"(b));
    return r;
}
__device__ __forceinline__ float2 unpack2(ull v) {
    float2 f;
    asm("mov.b64 {%0, %1}, %2;" : "=f"(f.x), "=f"(f.y) : "l"(v));
    return f;
}

// ---------------- sequential recurrence ----------------
// 256 threads: h = t&3 (K quarter, interleaved 16B chunks), cg = t>>2 (0..63).
// Thread computes output cols nA=cg, nB=cg+64 (each 16B x-load feeds 4 FFMA2).
// Chunk i of slice h covers floats k = 4h+16i..+3 (i = 0..7) per side.
// Smem reads are PLAIN C++ loads (no volatile) so ptxas can hoist and
// software-pipeline them across the FMA stream.
// Reduction over the 4 h-lanes: two independent scalar shfl chains.
__global__ void __launch_bounds__(256, 1) recur_kernel(
    const float* __restrict__ emb,   // [B, L, E]
    const float* __restrict__ Ww,    // [2E, E]
    const float* __restrict__ Wb,    // [E]
    const int*   __restrict__ li,    // [NI]
    const int*   __restrict__ ri)    // [NI]
{
    __shared__ __align__(16) float cur[2][RPC][EE];    // double-buffered state
    __shared__ __align__(16) float leafs[2][RPC][EE];  // double-buffered right leaf
    __shared__ int ridx[NI + 1];

    const int t  = threadIdx.x;
    const int h  = t & 3;           // K-slice
    const int cg = t >> 2;          // 0..63
    const int nA = cg;
    const int nB = cg + 64;
    const int b0 = blockIdx.x * RPC;

    // Weight column slices in registers: 2 sides x 2 cols x 32 K-floats = 64 b64.
    ull wlA[16], wlB[16], wrA[16], wrB[16];
#pragma unroll
    for (int i = 0; i < 8; i++) {
        const int k0 = 4 * h + 16 * i;
        wlA[2*i]   = pack2(Ww[(size_t)(k0    ) * EE + nA], Ww[(size_t)(k0 + 1) * EE + nA]);
        wlA[2*i+1] = pack2(Ww[(size_t)(k0 + 2) * EE + nA], Ww[(size_t)(k0 + 3) * EE + nA]);
        wlB[2*i]   = pack2(Ww[(size_t)(k0    ) * EE + nB], Ww[(size_t)(k0 + 1) * EE + nB]);
        wlB[2*i+1] = pack2(Ww[(size_t)(k0 + 2) * EE + nB], Ww[(size_t)(k0 + 3) * EE + nB]);
        wrA[2*i]   = pack2(Ww[(size_t)(EE + k0    ) * EE + nA], Ww[(size_t)(EE + k0 + 1) * EE + nA]);
        wrA[2*i+1] = pack2(Ww[(size_t)(EE + k0 + 2) * EE + nA], Ww[(size_t)(EE + k0 + 3) * EE + nA]);
        wrB[2*i]   = pack2(Ww[(size_t)(EE + k0    ) * EE + nB], Ww[(size_t)(EE + k0 + 1) * EE + nB]);
        wrB[2*i+1] = pack2(Ww[(size_t)(EE + k0 + 2) * EE + nB], Ww[(size_t)(EE + k0 + 3) * EE + nB]);
    }
    const float biasA = Wb[nA];
    const float biasB = Wb[nB];

    // right-leaf indices into smem
    for (int j = t; j < NI; j += 256) ridx[j] = ri[j];
    if (t == 0) ridx[NI] = ri[0];   // dummy for prefetch overrun

    // init cur[0] = leaf(left_idx[0]); loader: 4 rows x 64 lanes x float2
    const int l0   = li[0];
    const int r_ld = t >> 6;
    const int c_ld = (t & 63) * 2;
    {
        const float2 v = *(const float2*)&emb[((size_t)(b0 + r_ld) * LL + l0) * EE + c_ld];
        cur[0][r_ld][c_ld]     = v.x;
        cur[0][r_ld][c_ld + 1] = v.y;
    }
    __syncthreads();

    // prefetch right leaf for step 0
    float2 lv = *(const float2*)&emb[((size_t)(b0 + r_ld) * LL + ridx[0]) * EE + c_ld];

    for (int j = 0; j < NI; j++) {
        const int rb = j & 1;           // read state buffer
        const int wb = rb ^ 1;          // write state buffer
        // commit prefetched leaf; one barrier covers leaf-ready + prev cur writes
        leafs[rb][r_ld][c_ld]     = lv.x;
        leafs[rb][r_ld][c_ld + 1] = lv.y;
        const int rnext = ridx[j + 1];
        __syncthreads();
        lv = *(const float2*)&emb[((size_t)(b0 + r_ld) * LL + rnext) * EE + c_ld];

        // ---- phase A: accumulate all rows (compiler-scheduled LDS) ----
        ull accA[RPC], accB[RPC];
#pragma unroll
        for (int r = 0; r < RPC; r++) {
            ull sA0 = 0ull, sA1 = 0ull, sB0 = 0ull, sB1 = 0ull;
            const ulonglong2* xl = (const ulonglong2*)cur[rb][r];
            const ulonglong2* xr = (const ulonglong2*)leafs[rb][r];
#pragma unroll
            for (int i = 0; i < 8; i++) {
                const ulonglong2 p = xl[h + 4 * i];
                fma2(sA0, p.x, wlA[2*i]); fma2(sA1, p.y, wlA[2*i+1]);
                fma2(sB0, p.x, wlB[2*i]); fma2(sB1, p.y, wlB[2*i+1]);
            }
#pragma unroll
            for (int i = 0; i < 8; i++) {
                const ulonglong2 p = xr[h + 4 * i];
                fma2(sA0, p.x, wrA[2*i]); fma2(sA1, p.y, wrA[2*i+1]);
                fma2(sB0, p.x, wrB[2*i]); fma2(sB1, p.y, wrB[2*i+1]);
            }
            accA[r] = add2(sA0, sA1);
            accB[r] = add2(sB0, sB1);
        }

        // ---- phase B: reduce + commit (independent scalar shuffle chains) ----
#pragma unroll
        for (int r = 0; r < RPC; r++) {
            const float2 fA = unpack2(accA[r]);
            const float2 fB = unpack2(accB[r]);
            float uA = fA.x + fA.y;
            float uB = fB.x + fB.y;
            uA += __shfl_xor_sync(0xFFFFFFFFu, uA, 1);
            uB += __shfl_xor_sync(0xFFFFFFFFu, uB, 1);
            uA += __shfl_xor_sync(0xFFFFFFFFu, uA, 2);
            uB += __shfl_xor_sync(0xFFFFFFFFu, uB, 2);  // all 4 h-lanes hold sums
            if (h == r) {
                const float vA = uA + biasA;
                const float vB = uB + biasB;
                cur[wb][r][nA] = vA;
                cur[wb][r][nB] = vB;
                float* gn = &g_nodes[((size_t)(b0 + r) * NI + j) * EE];
                gn[nA] = vA;
                gn[nB] = vB;
            }
        }
    }
}

// ---------------- parallel projection: op = node @ G_w + G_b ----------------
// 2 nodes per warp (2 outstanding LDG.128 -> DRAM latency shared)
__global__ void __launch_bounds__(256) proj_kernel(
    const float* __restrict__ Gw,   // [E, OPS]
    const float* __restrict__ Gb,   // [OPS]
    float* __restrict__ out,        // [B, NI, OPS]
    int total_pairs)
{
    __shared__ float gws[EE * OPS];
    __shared__ float gbs[OPS];
    const int t = threadIdx.x;
    for (int i = t; i < EE * OPS; i += blockDim.x) gws[i] = Gw[i];
    if (t < OPS) gbs[t] = Gb[t];
    __syncthreads();

    const int pair = blockIdx.x * (blockDim.x >> 5) + (t >> 5);
    if (pair >= total_pairs) return;
    const int lane  = t & 31;
    const size_t n0 = (size_t)pair * 2;

    const float4 x0 = *(const float4*)&g_nodes[n0 * EE + lane * 4];
    const float4 x1 = *(const float4*)&g_nodes[(n0 + 1) * EE + lane * 4];
    const float* g  = &gws[lane * 4 * OPS];

    float p0[OPS], p1[OPS];
#pragma unroll
    for (int o = 0; o < OPS; o++) {
        p0[o] = x0.x * g[o] + x0.y * g[OPS + o] + x0.z * g[2 * OPS + o] + x0.w * g[3 * OPS + o];
        p1[o] = x1.x * g[o] + x1.y * g[OPS + o] + x1.z * g[2 * OPS + o] + x1.w * g[3 * OPS + o];
    }
#pragma unroll
    for (int off = 16; off; off >>= 1)
#pragma unroll
        for (int o = 0; o < OPS; o++) {
            p0[o] += __shfl_xor_sync(0xFFFFFFFFu, p0[o], off);
            p1[o] += __shfl_xor_sync(0xFFFFFFFFu, p1[o], off);
        }

    if (lane == 0) {
        float* op = out + n0 * OPS;
#pragma unroll
        for (int o = 0; o < OPS; o++) { op[o] = p0[o] + gbs[o]; op[OPS + o] = p1[o] + gbs[o]; }
    }
}

// ---------------- labels tail ----------------
// Labels land on device as int32 (JAX x64 disabled). mode 1: float cast.
// mode 2: widen to raw int64.
__global__ void tail_kernel(const int* __restrict__ labels, float* __restrict__ out, int mode)
{
    const int j = blockIdx.x * blockDim.x + threadIdx.x;
    if (j >= NI) return;
    const size_t base = (size_t)BB * NI * OPS;
    if (mode == 1) {
        out[base + j] = (float)labels[j];
    } else {
        ((long long*)(out + base))[j] = (long long)labels[j];
    }
}

extern "C" void kernel_launch(void* const* d_in, const int* in_sizes, int n_in,
                              void* d_out, int out_size)
{
    const float* emb    = (const float*)d_in[0];
    const float* Ww     = (const float*)d_in[1];
    const float* Wb     = (const float*)d_in[2];
    const float* Gw     = (const float*)d_in[3];
    const float* Gb     = (const float*)d_in[4];
    const int*   li     = (const int*)d_in[5];
    const int*   ri     = (const int*)d_in[6];
    const int*   labels = (const int*)d_in[7];
    float*       out    = (float*)d_out;

    recur_kernel<<<BB / RPC, 256>>>(emb, Ww, Wb, li, ri);

    const int total_pairs = BB * NI / 2;                    // 130816
    proj_kernel<<<total_pairs / 8, 256>>>(Gw, Gb, out, total_pairs); // 8 warps/block

    const long long base = (long long)BB * NI * OPS;
    const long long tail = (long long)out_size - base;
    if (tail == NI)          tail_kernel<<<2, 256>>>(labels, out, 1);
    else if (tail == 2 * NI) tail_kernel<<<2, 256>>>(labels, out, 2);
}